// round 1
// baseline (speedup 1.0000x reference)
#include <cuda_runtime.h>

// EvalBspPrimeTF: derivative of Bernstein basis of order 16 at 4M points.
// out[i][m] = d/dy B_{m,16}(y_i) expressed via integer-parameter Beta pdfs.
//
// Closed form (scale = 1):
//   out[0]  = -16 * (1-y)^15
//   out[m]  =  16 * ( C(15,m-1) y^(m-1) (1-y)^(16-m) - C(15,m) y^m (1-y)^(15-m) ),  1<=m<=15
//   out[16] =  16 * y^15
// Reference NaN->0 semantics: at y==0 rows, out[0]=out[1]=0; at y==1, out[15]=out[16]=0.

#define TPB 256
#define NCOL 17

__global__ __launch_bounds__(TPB)
void evalbspprime_kernel(const float* __restrict__ x,
                         float* __restrict__ out,
                         int n)
{
    __shared__ float s[TPB * NCOL];   // 17408 bytes, 16B-aligned segments per block

    const float C15[16] = {
        1.f, 15.f, 105.f, 455.f, 1365.f, 3003.f, 5005.f, 6435.f,
        6435.f, 5005.f, 3003.f, 1365.f, 455.f, 105.f, 15.f, 1.f
    };

    const int base = blockIdx.x * TPB;
    const int tid  = threadIdx.x;
    const int idx  = base + tid;

    float y = (idx < n) ? x[idx] : 0.5f;
    float q = 1.0f - y;

    // power ladders y^0..y^15, (1-y)^0..(1-y)^15
    float yp[16], qp[16];
    yp[0] = 1.0f; qp[0] = 1.0f;
#pragma unroll
    for (int k = 1; k < 16; ++k) {
        yp[k] = yp[k - 1] * y;
        qp[k] = qp[k - 1] * q;
    }

    float o[NCOL];
    o[0]  = -16.0f * qp[15];
#pragma unroll
    for (int m = 1; m < 16; ++m) {
        o[m] = 16.0f * (C15[m - 1] * yp[m - 1] * qp[16 - m]
                      - C15[m]     * yp[m]     * qp[15 - m]);
    }
    o[16] = 16.0f * yp[15];

    // match reference's 0*log(0) = nan -> 0 behavior at the support edges
    if (y == 0.0f) { o[0]  = 0.0f; o[1]  = 0.0f; }
    if (y == 1.0f) { o[15] = 0.0f; o[16] = 0.0f; }

    // stage in smem: stride 17 is coprime with 32 banks -> conflict-free
#pragma unroll
    for (int m = 0; m < NCOL; ++m)
        s[tid * NCOL + m] = o[m];

    __syncthreads();

    // coalesced vectorized writeback; block segment byte offset = blockIdx*17408 (16B aligned)
    const long long obase = (long long)base * NCOL;
    if (base + TPB <= n) {
        float4* __restrict__ o4 = reinterpret_cast<float4*>(out + obase);
        const float4* __restrict__ s4 = reinterpret_cast<const float4*>(s);
        const int n4 = (TPB * NCOL) / 4;   // 1088
#pragma unroll
        for (int i = tid; i < n4; i += TPB)
            o4[i] = s4[i];
    } else {
        const int rem = (n - base) * NCOL;
        for (int i = tid; i < rem; i += TPB)
            out[obase + i] = s[i];
    }
}

extern "C" void kernel_launch(void* const* d_in, const int* in_sizes, int n_in,
                              void* d_out, int out_size)
{
    const float* x = (const float*)d_in[0];
    float* out = (float*)d_out;
    const int n = in_sizes[0];          // 4,000,000 points
    const int blocks = (n + TPB - 1) / TPB;
    evalbspprime_kernel<<<blocks, TPB>>>(x, out, n);
}

// round 2
// speedup vs baseline: 1.0116x; 1.0116x over previous
#include <cuda_runtime.h>
#include <cstdint>

// EvalBspPrimeTF: derivative of Bernstein basis of order 16 at 4M points.
//   out[0]  = -16 * (1-y)^15
//   out[m]  =  16 * ( C(15,m-1) y^(m-1) (1-y)^(16-m) - C(15,m) y^m (1-y)^(15-m) ),  1<=m<=15
//   out[16] =  16 * y^15
// Reference NaN->0 semantics: at y==0, out[0]=out[1]=0; at y==1, out[15]=out[16]=0.
//
// R2: writeback via TMA bulk store (cp.async.bulk.global.shared::cta) — one
// 17408B burst per block instead of per-thread LDS+STG, cutting L1 work ~3x
// and decoupling the store stream from warp issue.

#define TPB 256
#define NCOL 17
#define TILE_BYTES (TPB * NCOL * 4)   // 17408, multiple of 16

__global__ __launch_bounds__(TPB)
void evalbspprime_kernel(const float* __restrict__ x,
                         float* __restrict__ out,
                         int n)
{
    __shared__ __align__(128) float s[TPB * NCOL];

    const float C15[16] = {
        1.f, 15.f, 105.f, 455.f, 1365.f, 3003.f, 5005.f, 6435.f,
        6435.f, 5005.f, 3003.f, 1365.f, 455.f, 105.f, 15.f, 1.f
    };

    const int base = blockIdx.x * TPB;
    const int tid  = threadIdx.x;
    const int idx  = base + tid;

    float y = (idx < n) ? x[idx] : 0.5f;
    float q = 1.0f - y;

    // power ladders y^0..y^15, (1-y)^0..(1-y)^15 (two independent chains)
    float yp[16], qp[16];
    yp[0] = 1.0f; qp[0] = 1.0f;
#pragma unroll
    for (int k = 1; k < 16; ++k) {
        yp[k] = yp[k - 1] * y;
        qp[k] = qp[k - 1] * q;
    }

    float o[NCOL];
    o[0]  = -16.0f * qp[15];
#pragma unroll
    for (int m = 1; m < 16; ++m) {
        o[m] = 16.0f * (C15[m - 1] * yp[m - 1] * qp[16 - m]
                      - C15[m]     * yp[m]     * qp[15 - m]);
    }
    o[16] = 16.0f * yp[15];

    // match reference's 0*log(0) = nan -> 0 behavior at the support edges
    if (y == 0.0f) { o[0]  = 0.0f; o[1]  = 0.0f; }
    if (y == 1.0f) { o[15] = 0.0f; o[16] = 0.0f; }

    // stage in smem: per-thread stride 17 words, coprime with 32 banks -> conflict-free,
    // each STS.32 wavefront moves a full 128B crossbar line.
#pragma unroll
    for (int m = 0; m < NCOL; ++m)
        s[tid * NCOL + m] = o[m];

    __syncthreads();

    if (base + TPB <= n) {
        // Single bulk async store: smem tile -> gmem, 17408B burst.
        if (tid == 0) {
            asm volatile("fence.proxy.async.shared::cta;" ::: "memory");
            uint32_t saddr = (uint32_t)__cvta_generic_to_shared(s);
            const float* g = out + (long long)base * NCOL;
            asm volatile(
                "cp.async.bulk.global.shared::cta.bulk_group [%0], [%1], %2;"
                :: "l"(g), "r"(saddr), "n"(TILE_BYTES) : "memory");
            asm volatile("cp.async.bulk.commit_group;" ::: "memory");
            // wait until the bulk engine has finished READING smem before the
            // block may exit (smem reuse safety).
            asm volatile("cp.async.bulk.wait_group.read 0;" ::: "memory");
        }
    } else {
        // tail (not taken for n = 4,000,000): scalar coalesced fallback
        const long long obase = (long long)base * NCOL;
        const int rem = (n - base) * NCOL;
        for (int i = tid; i < rem; i += TPB)
            out[obase + i] = s[i];
    }
}

extern "C" void kernel_launch(void* const* d_in, const int* in_sizes, int n_in,
                              void* d_out, int out_size)
{
    const float* x = (const float*)d_in[0];
    float* out = (float*)d_out;
    const int n = in_sizes[0];          // 4,000,000 points
    const int blocks = (n + TPB - 1) / TPB;
    evalbspprime_kernel<<<blocks, TPB>>>(x, out, n);
}